// round 2
// baseline (speedup 1.0000x reference)
#include <cuda_runtime.h>
#include <math.h>

#define BB  4
#define NN  4096
#define NGG 4096
#define NUU 8192
#define KK  6

// ---------------- scratch (device globals; no allocation allowed) ----------
__device__ float4 g_ori4[BB*NN];     // normalized ori_pre
__device__ float4 g_norpre4[BB*NN];  // normalized nor_pre
__device__ float4 g_oripro4[BB*NN];  // projected+normalized ori
__device__ float4 g_norgt4[BB*NN];   // gathered gt normals
__device__ unsigned long long g_amin[BB*NN];
__device__ float g_rm_up_q[BB*NUU];
__device__ float g_rm_up_g[BB*NGG];
__device__ float g_rm_of_q[BB*NUU];
__device__ float g_rm_of_g[BB*NGG];
__device__ double g_acc[4];          // 0: loss_nor sum, 1: loss_nor_ori sum, 2: smooth sum

// ---------------- helpers ---------------------------------------------------
__device__ __forceinline__ double blockReduceSum(double v) {
    __shared__ double sh[32];
    __syncthreads();                       // safe reuse between calls
    int lane = threadIdx.x & 31, w = threadIdx.x >> 5;
    #pragma unroll
    for (int o = 16; o; o >>= 1) v += __shfl_down_sync(0xffffffffu, v, o);
    if (lane == 0) sh[w] = v;
    __syncthreads();
    int nw = (blockDim.x + 31) >> 5;
    v = (threadIdx.x < nw) ? sh[threadIdx.x] : 0.0;
    if (w == 0) {
        #pragma unroll
        for (int o = 16; o; o >>= 1) v += __shfl_down_sync(0xffffffffu, v, o);
    }
    return v;
}

// ---------------- kernels ---------------------------------------------------
__global__ void k_init() {
    int i = blockIdx.x * blockDim.x + threadIdx.x;
    int stride = gridDim.x * blockDim.x;
    const float INF = __int_as_float(0x7f800000);
    for (int j = i; j < BB*NN; j += stride) g_amin[j] = ~0ull;
    for (int j = i; j < BB*NUU; j += stride) { g_rm_up_q[j] = INF; g_rm_of_q[j] = INF; }
    for (int j = i; j < BB*NGG; j += stride) { g_rm_up_g[j] = INF; g_rm_of_g[j] = INF; }
    if (i < 4) g_acc[i] = 0.0;
}

__global__ void k_norm(const float* __restrict__ ori, const float* __restrict__ nor) {
    int i = blockIdx.x * blockDim.x + threadIdx.x;
    if (i >= BB*NN) return;
    {
        float x = ori[3*i], y = ori[3*i+1], z = ori[3*i+2];
        float n = sqrtf(x*x + y*y + z*z + 1e-8f) + 1e-10f;
        g_ori4[i] = make_float4(x/n, y/n, z/n, 0.f);
    }
    {
        float x = nor[3*i], y = nor[3*i+1], z = nor[3*i+2];
        float n = sqrtf(x*x + y*y + z*z + 1e-8f) + 1e-10f;
        g_norpre4[i] = make_float4(x/n, y/n, z/n, 0.f);
    }
}

// argmin(pts vs gt.xyz): grid = BB*(NN/512)*4 = 128 blocks, 256 threads, QPT=2
__global__ void k_argmin(const float* __restrict__ pts, const float* __restrict__ gt) {
    __shared__ float4 s[1024];
    const int TS = 4, QCH = NN/512;
    int bx = blockIdx.x;
    int b   = bx / (QCH*TS);
    int rem = bx % (QCH*TS);
    int qc  = rem / TS;
    int tc  = rem % TS;
    int tbase = tc * 1024;
    for (int j = threadIdx.x; j < 1024; j += 256) {
        const float* gp = gt + (size_t)(b*NGG + tbase + j) * 6;
        float x = gp[0], y = gp[1], z = gp[2];
        s[j] = make_float4(x, y, z, fmaf(x, x, fmaf(y, y, z*z)));
    }
    __syncthreads();
    int q0 = qc*512 + threadIdx.x;
    int q1 = q0 + 256;
    const float* p0 = pts + (size_t)(b*NN + q0) * 3;
    const float* p1 = pts + (size_t)(b*NN + q1) * 3;
    float a0x = p0[0], a0y = p0[1], a0z = p0[2];
    float a1x = p1[0], a1y = p1[1], a1z = p1[2];
    float best0 = 1e30f, best1 = 1e30f;
    int bi0 = 0, bi1 = 0;
    for (int j = 0; j < 1024; j++) {
        float4 T = s[j];
        float d0 = fmaf(-2.f, fmaf(a0x, T.x, fmaf(a0y, T.y, a0z*T.z)), T.w);
        float d1 = fmaf(-2.f, fmaf(a1x, T.x, fmaf(a1y, T.y, a1z*T.z)), T.w);
        if (d0 < best0) { best0 = d0; bi0 = tbase + j; }
        if (d1 < best1) { best1 = d1; bi1 = tbase + j; }
    }
    float na0 = fmaf(a0x, a0x, fmaf(a0y, a0y, a0z*a0z));
    float na1 = fmaf(a1x, a1x, fmaf(a1y, a1y, a1z*a1z));
    float v0 = fmaxf(best0 + na0, 0.f);
    float v1 = fmaxf(best1 + na1, 0.f);
    unsigned long long k0 = ((unsigned long long)__float_as_uint(v0) << 32) | (unsigned)bi0;
    unsigned long long k1 = ((unsigned long long)__float_as_uint(v1) << 32) | (unsigned)bi1;
    atomicMin(&g_amin[b*NN + q0], k0);
    atomicMin(&g_amin[b*NN + q1], k1);
}

// per-point: gather normal, projection, loss_nor / loss_nor_ori terms
__global__ void k_post(const float* __restrict__ gt) {
    int i = blockIdx.x * blockDim.x + threadIdx.x;   // 64*256 = 16384 exact
    int b = i / NN;
    unsigned gidx = (unsigned)(g_amin[i] & 0xffffffffu);
    const float* gp = gt + (size_t)(b*NGG + gidx) * 6;
    float gx = gp[3], gy = gp[4], gz = gp[5];
    float4 o = g_ori4[i];
    float dn = fmaf(o.x, gx, fmaf(o.y, gy, o.z*gz));
    float vx = o.x - gx*dn, vy = o.y - gy*dn, vz = o.z - gz*dn;
    float nv = sqrtf(fmaf(vx, vx, fmaf(vy, vy, vz*vz)) + 1e-8f) + 1e-10f;
    g_oripro4[i] = make_float4(vx/nv, vy/nv, vz/nv, 0.f);
    g_norgt4[i]  = make_float4(gx, gy, gz, 0.f);
    float4 p = g_norpre4[i];
    float dpn = fmaf(gx, p.x, fmaf(gy, p.y, gz*p.z));
    float na = fmaxf(sqrtf(fmaf(gx, gx, fmaf(gy, gy, gz*gz))), 1e-8f);
    float nb = fmaxf(sqrtf(fmaf(p.x, p.x, fmaf(p.y, p.y, p.z*p.z))), 1e-8f);
    double t_nor = 1.0 - (double)fabsf(dpn / (na*nb));
    double t_ori = (double)fabsf(dn);
    double s1 = blockReduceSum(t_nor);
    double s2 = blockReduceSum(t_ori);
    if (threadIdx.x == 0) {
        atomicAdd(&g_acc[0], s1);
        atomicAdd(&g_acc[1], s2);
    }
}

// kNN top-6 (pts vs pts) + smoothness loss. grid = BB*(NN/128)=128 blocks, 128 thr
__global__ void k_knn(const float* __restrict__ pts) {
    __shared__ float4 s[2048];
    int b  = blockIdx.x / (NN/128);
    int qc = blockIdx.x % (NN/128);
    int qi = qc*128 + threadIdx.x;
    const float* p = pts + (size_t)(b*NN + qi) * 3;
    float ax = p[0], ay = p[1], az = p[2];
    float bd[KK];
    int   bi[KK];
    #pragma unroll
    for (int k = 0; k < KK; k++) { bd[k] = 1e30f; bi[k] = 0; }
    for (int ph = 0; ph < 2; ph++) {
        for (int j = threadIdx.x; j < 2048; j += 128) {
            const float* tp = pts + (size_t)(b*NN + ph*2048 + j) * 3;
            float x = tp[0], y = tp[1], z = tp[2];
            s[j] = make_float4(x, y, z, fmaf(x, x, fmaf(y, y, z*z)));
        }
        __syncthreads();
        for (int j = 0; j < 2048; j++) {
            float4 T = s[j];
            float d = fmaf(-2.f, fmaf(ax, T.x, fmaf(ay, T.y, az*T.z)), T.w);
            if (d < bd[KK-1]) {
                bd[KK-1] = d; bi[KK-1] = ph*2048 + j;
                #pragma unroll
                for (int k = KK-1; k > 0; k--) {
                    if (bd[k] < bd[k-1]) {
                        float td = bd[k]; bd[k] = bd[k-1]; bd[k-1] = td;
                        int   ti = bi[k]; bi[k] = bi[k-1]; bi[k-1] = ti;
                    }
                }
            }
        }
        __syncthreads();
    }
    // smoothness contribution for this query point
    int base = b*NN;
    float4 P = g_oripro4[base + qi];
    float4 G = g_norgt4[base + qi];
    float Rx = P.y*G.z - P.z*G.y;
    float Ry = P.z*G.x - P.x*G.z;
    float Rz = P.x*G.y - P.y*G.x;
    float nP = fmaxf(sqrtf(fmaf(P.x, P.x, fmaf(P.y, P.y, P.z*P.z))), 1e-8f);
    float nR = fmaxf(sqrtf(fmaf(Rx, Rx, fmaf(Ry, Ry, Rz*Rz))), 1e-8f);
    double sum = 0.0;
    #pragma unroll
    for (int k = 0; k < KK; k++) {
        float4 go = g_oripro4[base + bi[k]];
        float4 gn = g_norgt4[base + bi[k]];
        float dnn = fmaf(gn.x, G.x, fmaf(gn.y, G.y, gn.z*G.z));
        float ndv = expf(-dnn / 0.3f) * 10.f + 1.f;
        float w = (ndv < 4.f) ? 1.f : 5.f;
        float ngo = fmaxf(sqrtf(fmaf(go.x, go.x, fmaf(go.y, go.y, go.z*go.z))), 1e-8f);
        float c0 = fmaf(go.x, P.x, fmaf(go.y, P.y, go.z*P.z)) / (ngo*nP);
        float c1 = fmaf(go.x, Rx, fmaf(go.y, Ry, go.z*Rz)) / (ngo*nR);
        float c = fminf(1.f - fabsf(c0), 1.f - fabsf(c1));
        sum += (double)(w * c);
    }
    double tot = blockReduceSum(sum);
    if (threadIdx.x == 0) atomicAdd(&g_acc[2], tot);
}

// chamfer row-min: queries (stride qs) vs targets (stride ts), 256 threads, QPT=4
__global__ void k_chamfer(const float* __restrict__ q, int nq, int qs,
                          const float* __restrict__ t, int nt, int ts,
                          int tsplit, int which) {
    __shared__ float4 s[1024];
    float* rowmin = (which == 0) ? g_rm_up_q :
                    (which == 1) ? g_rm_up_g :
                    (which == 2) ? g_rm_of_q : g_rm_of_g;
    const int QPT = 4;
    int qpb = 256 * QPT;
    int qch = nq / qpb;
    int bx  = blockIdx.x;
    int b   = bx / (qch * tsplit);
    int rem = bx % (qch * tsplit);
    int qc  = rem / tsplit;
    int tc  = rem % tsplit;
    int tile  = nt / tsplit;   // == 1024
    int tbase = tc * tile;
    for (int j = threadIdx.x; j < tile; j += 256) {
        const float* tp = t + (size_t)(b*nt + tbase + j) * ts;
        float x = tp[0], y = tp[1], z = tp[2];
        s[j] = make_float4(x, y, z, fmaf(x, x, fmaf(y, y, z*z)));
    }
    __syncthreads();
    float qx[QPT], qy[QPT], qz[QPT], mn[QPT];
    int qbase = qc * qpb;
    #pragma unroll
    for (int l = 0; l < QPT; l++) {
        int qi = qbase + l*256 + threadIdx.x;
        const float* qp = q + (size_t)(b*nq + qi) * qs;
        qx[l] = qp[0]; qy[l] = qp[1]; qz[l] = qp[2];
        mn[l] = 1e30f;
    }
    for (int j = 0; j < tile; j++) {
        float4 T = s[j];
        #pragma unroll
        for (int l = 0; l < QPT; l++) {
            float d = fmaf(-2.f, fmaf(qx[l], T.x, fmaf(qy[l], T.y, qz[l]*T.z)), T.w);
            mn[l] = fminf(mn[l], d);
        }
    }
    #pragma unroll
    for (int l = 0; l < QPT; l++) {
        int qi = qbase + l*256 + threadIdx.x;
        float na = fmaf(qx[l], qx[l], fmaf(qy[l], qy[l], qz[l]*qz[l]));
        float v = fmaxf(mn[l] + na, 0.f);
        atomicMin((int*)&rowmin[b*nq + qi], __float_as_int(v));
    }
}

__global__ void k_final(float* __restrict__ out) {
    double s;
    s = 0.0; for (int j = threadIdx.x; j < BB*NUU; j += 256) s += (double)g_rm_up_q[j];
    double up_q = blockReduceSum(s);
    s = 0.0; for (int j = threadIdx.x; j < BB*NGG; j += 256) s += (double)g_rm_up_g[j];
    double up_g = blockReduceSum(s);
    s = 0.0; for (int j = threadIdx.x; j < BB*NUU; j += 256) s += (double)g_rm_of_q[j];
    double of_q = blockReduceSum(s);
    s = 0.0; for (int j = threadIdx.x; j < BB*NGG; j += 256) s += (double)g_rm_of_g[j];
    double of_g = blockReduceSum(s);
    if (threadIdx.x == 0) {
        double loss_nor     = g_acc[0] / (double)(BB*NN);
        double loss_nor_ori = g_acc[1] / (double)(BB*NN);
        double loss_smooth  = g_acc[2] / (double)(BB*NN*KK);
        double lco = of_q / (double)(BB*NUU) + of_g / (double)(BB*NGG);
        double lc  = up_q / (double)(BB*NUU) + up_g / (double)(BB*NGG);
        double loss_cd = lc + 0.4 * lco;
        double loss = loss_smooth + loss_nor + 0.1 * loss_nor_ori + 200.0 * loss_cd;
        out[0] = (float)loss;
        out[1] = (float)loss_smooth;
        out[2] = (float)loss_nor;
        out[3] = (float)lco;
        out[4] = (float)loss_nor_ori;
        out[5] = (float)lc;
        out[6] = (float)lc;
    }
}

// ---------------- launch ----------------------------------------------------
extern "C" void kernel_launch(void* const* d_in, const int* in_sizes, int n_in,
                              void* d_out, int out_size) {
    const float* ori = (const float*)d_in[0];
    const float* nor = (const float*)d_in[1];
    const float* up  = (const float*)d_in[2];
    const float* off = (const float*)d_in[3];
    const float* pts = (const float*)d_in[4];
    const float* gt  = (const float*)d_in[5];
    float* out = (float*)d_out;

    k_init<<<64, 256>>>();
    k_norm<<<64, 256>>>(ori, nor);
    k_argmin<<<128, 256>>>(pts, gt);
    k_post<<<64, 256>>>(gt);
    k_knn<<<128, 128>>>(pts);
    // up -> gt  (nq=NUU stride3, nt=NGG stride6, tsplit=4): 4*8*4 = 128 blocks
    k_chamfer<<<128, 256>>>(up,  NUU, 3, gt,  NGG, 6, 4, 0);
    // gt -> up  (nq=NGG stride6, nt=NUU stride3, tsplit=8): 4*4*8 = 128 blocks
    k_chamfer<<<128, 256>>>(gt,  NGG, 6, up,  NUU, 3, 8, 1);
    // off -> gt
    k_chamfer<<<128, 256>>>(off, NUU, 3, gt,  NGG, 6, 4, 2);
    // gt -> off
    k_chamfer<<<128, 256>>>(gt,  NGG, 6, off, NUU, 3, 8, 3);
    k_final<<<1, 256>>>(out);
}